// round 3
// baseline (speedup 1.0000x reference)
#include <cuda_runtime.h>
#include <math.h>

// ---------------- problem constants ----------------
#define BATCH   64
#define SEQ     512
#define EMB     256
#define HID     512
#define GATES   2048           // 4*HID
#define VOCAB   50257
#define NBLK    128            // persistent LSTM grid (<=148 SMs, 1 block/SM)

// ---------------- device scratch (static, no allocs) ----------------
__device__ float g_Z[(size_t)SEQ * BATCH * GATES];   // 256 MB: x@Wi + b, [s][b][4H]
__device__ float g_h[2][BATCH * HID];                // hidden state, batch-major [b][u]
__device__ float g_y1[BATCH * HID];
__device__ float g_y2[BATCH * HID];
__device__ float g_logits[(size_t)BATCH * VOCAB];
__device__ unsigned g_bar_cnt   = 0;
__device__ unsigned g_bar_sense = 0;

// ---------------- packed f32x2 helpers (FFMA2 path, sm_100+) --------------
__device__ __forceinline__ unsigned long long fma2(unsigned long long a,
                                                   unsigned long long b,
                                                   unsigned long long c)
{
    unsigned long long d;
    asm("fma.rn.f32x2 %0, %1, %2, %3;" : "=l"(d) : "l"(a), "l"(b), "l"(c));
    return d;
}
__device__ __forceinline__ unsigned long long pack2(float x)
{
    unsigned long long d;
    unsigned u = __float_as_uint(x);
    asm("mov.b64 %0, {%1, %1};" : "=l"(d) : "r"(u));
    return d;
}
__device__ __forceinline__ float lo2(unsigned long long v) { return __uint_as_float((unsigned)v); }
__device__ __forceinline__ float hi2(unsigned long long v) { return __uint_as_float((unsigned)(v >> 32)); }

// ---------------- grid barrier (sense reversing) ----------
__device__ __forceinline__ void grid_barrier(unsigned &sense)
{
    __syncthreads();
    if (threadIdx.x == 0) {
        sense ^= 1u;
        __threadfence();
        if (atomicAdd(&g_bar_cnt, 1u) == NBLK - 1u) {
            atomicExch(&g_bar_cnt, 0u);
            __threadfence();
            atomicExch(&g_bar_sense, sense);
        } else {
            while (((volatile unsigned*)&g_bar_sense)[0] != sense) { }
            __threadfence();
        }
    }
    __syncthreads();
}

__device__ __forceinline__ float sigmoidf_(float x)
{
    return 1.0f / (1.0f + __expf(-x));
}

// ---------------- kernel 1: Z = gather(emb, inputs) @ Wi + b --------------
// 128x128 block tile, K-chunks of 16, 8x8 thread tile via f32x2.
// grid (16, 256), 256 threads, 2 blocks/SM.
__global__ void __launch_bounds__(256, 2)
embed_gemm_kernel(const int* __restrict__ inputs, const float* __restrict__ emb,
                  const float* __restrict__ Wi, const float* __restrict__ bias)
{
    __shared__ float As[128][17];    // [m][k]
    __shared__ float Bs[16][132];    // [k][n]

    const int t  = threadIdx.x;
    const int mt = blockIdx.y;       // 0..255
    const int nt = blockIdx.x;       // 0..15
    const int tx = t & 15;           // n dir
    const int ty = t >> 4;           // m dir

    const int ra   = t >> 1;
    const int koff = (t & 1) * 8;
    const int rowg = mt * 128 + ra;
    const int s    = rowg >> 6;
    const int b    = rowg & 63;
    const float* erow = emb + (size_t)inputs[b * SEQ + s] * EMB;

    const int bkr  = t >> 4;
    const int bcol = (t & 15) * 8;

    unsigned long long acc[8][4];
#pragma unroll
    for (int i = 0; i < 8; ++i)
#pragma unroll
        for (int j = 0; j < 4; ++j) acc[i][j] = 0ULL;

    for (int k0 = 0; k0 < EMB; k0 += 16) {
        {
            float4 a0 = *(const float4*)(erow + k0 + koff);
            float4 a1 = *(const float4*)(erow + k0 + koff + 4);
            As[ra][koff + 0] = a0.x; As[ra][koff + 1] = a0.y;
            As[ra][koff + 2] = a0.z; As[ra][koff + 3] = a0.w;
            As[ra][koff + 4] = a1.x; As[ra][koff + 5] = a1.y;
            As[ra][koff + 6] = a1.z; As[ra][koff + 7] = a1.w;
        }
        {
            const float* wsrc = Wi + (size_t)(k0 + bkr) * GATES + nt * 128 + bcol;
            float4 b0v = *(const float4*)(wsrc);
            float4 b1v = *(const float4*)(wsrc + 4);
            *(float4*)&Bs[bkr][bcol]     = b0v;
            *(float4*)&Bs[bkr][bcol + 4] = b1v;
        }
        __syncthreads();

#pragma unroll
        for (int k = 0; k < 16; ++k) {
            unsigned long long pa[8];
#pragma unroll
            for (int i = 0; i < 4; ++i) {
                pa[i]     = pack2(As[ty * 4 + i][k]);
                pa[i + 4] = pack2(As[64 + ty * 4 + i][k]);
            }
            ulonglong2 b0v = *(const ulonglong2*)&Bs[k][tx * 4];
            ulonglong2 b1v = *(const ulonglong2*)&Bs[k][64 + tx * 4];
#pragma unroll
            for (int i = 0; i < 8; ++i) {
                acc[i][0] = fma2(pa[i], b0v.x, acc[i][0]);
                acc[i][1] = fma2(pa[i], b0v.y, acc[i][1]);
                acc[i][2] = fma2(pa[i], b1v.x, acc[i][2]);
                acc[i][3] = fma2(pa[i], b1v.y, acc[i][3]);
            }
        }
        __syncthreads();
    }

    float4 bb0 = *(const float4*)(bias + nt * 128 + tx * 4);
    float4 bb1 = *(const float4*)(bias + nt * 128 + 64 + tx * 4);
#pragma unroll
    for (int i = 0; i < 8; ++i) {
        int row = mt * 128 + ((i < 4) ? (ty * 4 + i) : (64 + ty * 4 + i - 4));
        float* zr = g_Z + (size_t)row * GATES + nt * 128;
        float4 v0, v1;
        v0.x = lo2(acc[i][0]) + bb0.x; v0.y = hi2(acc[i][0]) + bb0.y;
        v0.z = lo2(acc[i][1]) + bb0.z; v0.w = hi2(acc[i][1]) + bb0.w;
        v1.x = lo2(acc[i][2]) + bb1.x; v1.y = hi2(acc[i][2]) + bb1.y;
        v1.z = lo2(acc[i][3]) + bb1.z; v1.w = hi2(acc[i][3]) + bb1.w;
        *(float4*)(zr + tx * 4)      = v0;
        *(float4*)(zr + 64 + tx * 4) = v1;
    }
}

// ---------------- kernel 2: persistent LSTM over 512 steps ----------------
// 128 blocks = 64 unit-groups x 2 batch-halves. Block: 8 units x 32 batches.
// Thread = one (unit, batch) pair, full K=512, c in register, no reduction.
// smem: h_s [32 batches][512 k] (64KB) + Whs [512 k][8 u]{i,f,g,o} (64KB).
#define LSTM_SMEM (131072)

__global__ void __launch_bounds__(256, 1)
lstm_kernel(const float* __restrict__ Wh)
{
    extern __shared__ float sm[];
    float*      h_s = sm;                          // [32][512]
    ulonglong2* Whs = (ulonglong2*)(sm + 32 * HID); // [512][8]: .x=(wi,wf) .y=(wg,wo)

    const int tid = threadIdx.x;
    const int u   = tid & 7;           // unit within block (0..7)
    const int bl  = tid >> 3;          // local batch (0..31)
    const int ub  = blockIdx.x >> 1;   // unit group (0..63)
    const int bb  = blockIdx.x & 1;    // batch half (0..1)
    const int uu  = ub * 8 + u;        // global unit
    const int gb  = bb * 32 + bl;      // global batch

    // stage Wh slice (one-time): Whs[k][u2] = {(wi,wf),(wg,wo)} for col=ub*8+u2
    for (int i = tid; i < HID * 8; i += 256) {
        int k   = i >> 3;
        int u2  = i & 7;
        const float* w = Wh + (size_t)k * GATES + ub * 8 + u2;
        float wi = w[0], wf = w[512], wg = w[1024], wo = w[1536];
        float4 v = make_float4(wi, wf, wg, wo);
        Whs[(size_t)k * 8 + u2] = *(ulonglong2*)&v;
    }
    // zero h_s (step 0 uses zeros)
    {
        float4 z4 = make_float4(0.f, 0.f, 0.f, 0.f);
        float4* dst = (float4*)h_s;
#pragma unroll
        for (int q = 0; q < 16; ++q) dst[tid + q * 256] = z4;
    }

    float c = 0.0f;
    unsigned sense = 0;
    __syncthreads();

    const ulonglong2* wp = Whs + u;                      // stride 8 per k
    const float4*     hp = (const float4*)(h_s + bl * HID);

    for (int s = 0; s < SEQ; ++s) {
        // stage h_{s-1}: contiguous 64KB slice of g_h (batch-major), coalesced
        if (s > 0) {
            const float4* src = (const float4*)(g_h[s & 1] + bb * 32 * HID);
            float4* dst = (float4*)h_s;
#pragma unroll 8
            for (int q = 0; q < 16; ++q)
                dst[tid + q * 256] = __ldcg(src + tid + q * 256);
        }

        // Z gates for this (batch, unit) — issue early, latency overlaps
        const float* z = g_Z + ((size_t)s * BATCH + gb) * GATES + uu;
        float zi = __ldcg(z);
        float zf = __ldcg(z + 512);
        float zg = __ldcg(z + 1024);
        float zo = __ldcg(z + 1536);
        __syncthreads();

        unsigned long long aif = 0, ago = 0;
        if (s > 0) {
#pragma unroll 4
            for (int k4 = 0; k4 < 128; ++k4) {
                float4 hv = hp[k4];
                ulonglong2 w0 = wp[(k4 * 4 + 0) * 8];
                ulonglong2 w1 = wp[(k4 * 4 + 1) * 8];
                ulonglong2 w2 = wp[(k4 * 4 + 2) * 8];
                ulonglong2 w3 = wp[(k4 * 4 + 3) * 8];
                unsigned long long p;
                p = pack2(hv.x); aif = fma2(p, w0.x, aif); ago = fma2(p, w0.y, ago);
                p = pack2(hv.y); aif = fma2(p, w1.x, aif); ago = fma2(p, w1.y, ago);
                p = pack2(hv.z); aif = fma2(p, w2.x, aif); ago = fma2(p, w2.y, ago);
                p = pack2(hv.w); aif = fma2(p, w3.x, aif); ago = fma2(p, w3.y, ago);
            }
        }

        float ai = zi + lo2(aif);
        float af = zf + hi2(aif);
        float ag = zg + lo2(ago);
        float ao = zo + hi2(ago);

        float ig = sigmoidf_(ai);
        float fg = sigmoidf_(af);
        float gg = tanhf(ag);
        float og = sigmoidf_(ao);
        c = fg * c + ig * gg;
        float hv = og * tanhf(c);

        g_h[(s + 1) & 1][gb * HID + uu] = hv;   // final h lands in g_h[0]

        grid_barrier(sense);
    }
}

// ---------------- kernels 3/4: y = tanh(x @ W + bias), 64x512 --------------
__global__ void __launch_bounds__(256)
fc_tanh_kernel(const float* __restrict__ x, const float* __restrict__ W,
               const float* __restrict__ bias, float* __restrict__ y)
{
    int o = blockIdx.x * blockDim.x + threadIdx.x;   // 32768 threads
    int b = o >> 9, j = o & 511;
    const float* xp = x + b * HID;
    float a0 = 0.f, a1 = 0.f, a2 = 0.f, a3 = 0.f;
#pragma unroll 4
    for (int k = 0; k < HID; k += 4) {
        a0 += xp[k + 0] * W[(size_t)(k + 0) * HID + j];
        a1 += xp[k + 1] * W[(size_t)(k + 1) * HID + j];
        a2 += xp[k + 2] * W[(size_t)(k + 2) * HID + j];
        a3 += xp[k + 3] * W[(size_t)(k + 3) * HID + j];
    }
    y[o] = tanhf((a0 + a1) + (a2 + a3) + bias[j]);
}

// ---------------- kernel 5: logits = y2 @ W3 + b3 ----------------
__global__ void __launch_bounds__(128)
logits_kernel(const float* __restrict__ y, const float* __restrict__ W3,
              const float* __restrict__ b3, float* __restrict__ out)
{
    __shared__ float ys[128][68];   // [k-chunk][b] transposed, padded
    const int j = blockIdx.x * 128 + threadIdx.x;

    float acc[64];
#pragma unroll
    for (int b = 0; b < 64; ++b) acc[b] = 0.0f;

    for (int kc = 0; kc < HID; kc += 128) {
        __syncthreads();
        for (int q = threadIdx.x; q < 128 * 64; q += 128) {
            int b = q >> 7, k = q & 127;
            ys[k][b] = y[b * HID + kc + k];
        }
        __syncthreads();
        if (j < VOCAB) {
#pragma unroll 4
            for (int k = 0; k < 128; ++k) {
                float w = W3[(size_t)(kc + k) * VOCAB + j];
                const float4* yr = (const float4*)&ys[k][0];
#pragma unroll
                for (int b4 = 0; b4 < 16; ++b4) {
                    float4 v = yr[b4];
                    acc[b4 * 4 + 0] += v.x * w;
                    acc[b4 * 4 + 1] += v.y * w;
                    acc[b4 * 4 + 2] += v.z * w;
                    acc[b4 * 4 + 3] += v.w * w;
                }
            }
        }
    }
    if (j < VOCAB) {
        float bb = b3[j];
#pragma unroll
        for (int b = 0; b < 64; ++b)
            out[(size_t)b * VOCAB + j] = acc[b] + bb;
    }
}

// ---------------- kernel 6: row-wise log_softmax ----------------
__global__ void __launch_bounds__(1024)
logsoftmax_kernel(const float* __restrict__ logits, float* __restrict__ out)
{
    __shared__ float red[32];
    const int b = blockIdx.x;
    const float* row  = logits + (size_t)b * VOCAB;
    float*       orow = out    + (size_t)b * VOCAB;
    const int tid = threadIdx.x;

    float m = -1e30f;
    for (int j = tid; j < VOCAB; j += 1024) m = fmaxf(m, row[j]);
#pragma unroll
    for (int o = 16; o; o >>= 1) m = fmaxf(m, __shfl_xor_sync(0xffffffffu, m, o));
    if ((tid & 31) == 0) red[tid >> 5] = m;
    __syncthreads();
    if (tid < 32) {
        float v = red[tid];
#pragma unroll
        for (int o = 16; o; o >>= 1) v = fmaxf(v, __shfl_xor_sync(0xffffffffu, v, o));
        red[tid] = v;
    }
    __syncthreads();
    m = red[0];

    float sum = 0.0f;
    for (int j = tid; j < VOCAB; j += 1024) sum += __expf(row[j] - m);
#pragma unroll
    for (int o = 16; o; o >>= 1) sum += __shfl_xor_sync(0xffffffffu, sum, o);
    __syncthreads();
    if ((tid & 31) == 0) red[tid >> 5] = sum;
    __syncthreads();
    if (tid < 32) {
        float v = red[tid];
#pragma unroll
        for (int o = 16; o; o >>= 1) v += __shfl_xor_sync(0xffffffffu, v, o);
        red[tid] = v;
    }
    __syncthreads();
    float lse = m + logf(red[0]);

    for (int j = tid; j < VOCAB; j += 1024) orow[j] = row[j] - lse;
}

// ---------------- launch ----------------
extern "C" void kernel_launch(void* const* d_in, const int* in_sizes, int n_in,
                              void* d_out, int out_size)
{
    const int*   inputs = (const int*)  d_in[0];
    const float* emb    = (const float*)d_in[1];
    const float* Wi     = (const float*)d_in[2];
    const float* Wh     = (const float*)d_in[3];
    const float* bvec   = (const float*)d_in[4];
    const float* W1     = (const float*)d_in[5];
    const float* b1     = (const float*)d_in[6];
    const float* W2     = (const float*)d_in[7];
    const float* b2     = (const float*)d_in[8];
    const float* W3     = (const float*)d_in[9];
    const float* b3     = (const float*)d_in[10];
    float* out = (float*)d_out;

    void *p_h = 0, *p_y1 = 0, *p_y2 = 0, *p_lg = 0;
    cudaGetSymbolAddress(&p_h,  g_h);      // final h lives in g_h[0], batch-major
    cudaGetSymbolAddress(&p_y1, g_y1);
    cudaGetSymbolAddress(&p_y2, g_y2);
    cudaGetSymbolAddress(&p_lg, g_logits);

    // 1. Z = emb[inputs] @ Wi + b  (time-parallel)
    embed_gemm_kernel<<<dim3(GATES / 128, (SEQ * BATCH) / 128), 256>>>(inputs, emb, Wi, bvec);

    // 2. persistent LSTM recurrence
    cudaFuncSetAttribute(lstm_kernel, cudaFuncAttributeMaxDynamicSharedMemorySize, LSTM_SMEM);
    lstm_kernel<<<NBLK, 256, LSTM_SMEM>>>(Wh);

    // 3/4. dense tanh layers (h is batch-major now)
    fc_tanh_kernel<<<128, 256>>>((const float*)p_h,  W1, b1, (float*)p_y1);
    fc_tanh_kernel<<<128, 256>>>((const float*)p_y1, W2, b2, (float*)p_y2);

    // 5. vocab projection
    logits_kernel<<<(VOCAB + 127) / 128, 128>>>((const float*)p_y2, W3, b3, (float*)p_lg);

    // 6. log_softmax
    logsoftmax_kernel<<<BATCH, 1024>>>((const float*)p_lg, out);
}